// round 9
// baseline (speedup 1.0000x reference)
#include <cuda_runtime.h>
#include <cstdint>

// SlidingGaussianWindow1d: out[b,w,c,d] = clip(corrcoef_t of x[b,t,:] * W[w,t])
// B=16, T=256, C=64, NWIN=224.
//
// Identities:
//  - W[w,t] = A[(t + S_w) mod 256], S_w = (w+1)(w-222)/2
//  - A = conv(gauss, box)/max ~0 outside a ~40-wide arc: truncate t-loop to
//    the support (found on device; chunked fallback for wide alpha).
//  - corr_cd = (S_cd - m_c m_d/T) * dinv_c * dinv_d (1/(T-1) cancels)
//
// R9: Gram matrices on legacy tensor cores (mma.sync.m16n8k16.bf16, base
// target legal). Split precision: y = hi + lo (both bf16), S ~= HtH+HtL+LtH.
// Fragments loaded with scalar LDS.32 per the PTX ISA layout (no ldmatrix).

#define T_LEN 256
#define C_DIM 64
#define NWIN  224
#define B_DIM 16
#define KCH   48            // K-chunk (padded); support arc fits in one chunk
#define HSTB  100           // Ht/Lt row stride in bytes (50 bf16, odd words)

__device__ float g_A[256];
__device__ int   g_ilo;
__device__ int   g_keff;

// ---------------------------------------------------------------------------
// Prep: A[t] from win_alpha; parallel support scan {i : A[i] > 1e-6}.
// ---------------------------------------------------------------------------
__global__ void prep_kernel(const float* __restrict__ alpha) {
    __shared__ float gw[256];
    __shared__ float Ac[511];
    __shared__ float red[64];
    __shared__ float sA[256];
    __shared__ float s_max;
    __shared__ unsigned int masks[8];
    int tid = threadIdx.x;  // 512 threads

    float a = alpha[0];
    float inv = 1.0f / (2.0f * a * a);
    if (tid < 256) {
        float d = (float)tid - 128.0f;
        gw[tid] = expf(-d * d) * inv;
    }
    __syncthreads();
    if (tid < 511) {
        int lo = tid - 143; if (lo < 0)   lo = 0;
        int hi = tid - 112; if (hi > 255) hi = 255;
        float s = 0.0f;
        for (int k = lo; k <= hi; k++) s += gw[k];
        Ac[tid] = s;
    }
    __syncthreads();
    if (tid < 64) {
        float m = 0.0f;
        for (int n = tid; n < 511; n += 64) m = fmaxf(m, Ac[n]);
        red[tid] = m;
    }
    __syncthreads();
    if (tid == 0) {
        float m = 0.0f;
        #pragma unroll
        for (int n = 0; n < 64; n++) m = fmaxf(m, red[n]);
        s_max = m;
    }
    __syncthreads();
    if (tid < 256) {
        float v = Ac[128 + tid] / s_max;
        sA[tid] = v;
        g_A[tid] = v;
    }
    __syncthreads();
    if (tid < 256) {
        unsigned int m = __ballot_sync(0xFFFFFFFFu, sA[tid] > 1e-6f);
        if ((tid & 31) == 0) masks[tid >> 5] = m;
    }
    __syncthreads();
    if (tid == 0) {
        int lo = 0, hi = 255;
        for (int k = 0; k < 8; k++)
            if (masks[k]) { lo = k * 32 + __ffs(masks[k]) - 1; break; }
        for (int k = 7; k >= 0; k--)
            if (masks[k]) { hi = k * 32 + 31 - __clz(masks[k]); break; }
        g_ilo  = lo;
        g_keff = hi - lo + 1;
    }
}

// ---------------------------------------------------------------------------
__device__ __forceinline__ void mma_bf16(float* d, const uint32_t* a, const uint32_t* b) {
    asm volatile(
        "mma.sync.aligned.m16n8k16.row.col.f32.bf16.bf16.f32 "
        "{%0,%1,%2,%3}, {%4,%5,%6,%7}, {%8,%9}, {%0,%1,%2,%3};"
        : "+f"(d[0]), "+f"(d[1]), "+f"(d[2]), "+f"(d[3])
        : "r"(a[0]), "r"(a[1]), "r"(a[2]), "r"(a[3]), "r"(b[0]), "r"(b[1]));
}
__device__ __forceinline__ uint32_t lds32(uint32_t addr) {
    uint32_t v;
    asm volatile("ld.shared.b32 %0, [%1];" : "=r"(v) : "r"(addr));
    return v;
}
__device__ __forceinline__ void sts32(uint32_t addr, uint32_t v) {
    asm volatile("st.shared.b32 [%0], %1;" :: "r"(addr), "r"(v));
}

// ---------------------------------------------------------------------------
// Main: 128 threads per (w, b). Warp wid owns c-strip [16wid, 16wid+16)
// (one m16 tile row) x all 64 d (8 n-tiles). 3 mma chains: HH, HL, LH.
// ---------------------------------------------------------------------------
__global__ __launch_bounds__(128) void corr_kernel(const float* __restrict__ x,
                                                   float* __restrict__ out) {
    __shared__ float    yst[KCH][64];              // 12 KB fp32 staging
    __shared__ uint32_t Hts[(64 * HSTB + 4) / 4];  // bf16 [c][k], stride 100B
    __shared__ uint32_t Lts[(64 * HSTB + 4) / 4];
    __shared__ float mpart[2][64];
    __shared__ float mcol[64];
    __shared__ float dinv[64];

    const int w    = blockIdx.x;
    const int b    = blockIdx.y;
    const int tid  = threadIdx.x;
    const int wid  = tid >> 5;
    const int lane = tid & 31;
    const int g    = lane >> 2;          // fragment group row
    const int tig  = lane & 3;           // thread-in-group

    int s = ((w + 1) * (w - 222)) / 2;   // cumulative roll (even product, exact)
    int smod = ((s % 256) + 256) & 255;

    const int ilo  = g_ilo;
    const int keff = g_keff;

    const float* xb = x + ((size_t)b << 14);
    const int m0 = wid << 4;

    const uint32_t ybase = (uint32_t)__cvta_generic_to_shared(&yst[0][0]);
    const uint32_t htb   = (uint32_t)__cvta_generic_to_shared(&Hts[0]);
    const uint32_t ltb   = (uint32_t)__cvta_generic_to_shared(&Lts[0]);

    float D[8][4];
    #pragma unroll
    for (int nt = 0; nt < 8; nt++)
        #pragma unroll
        for (int e = 0; e < 4; e++) D[nt][e] = 0.0f;
    float msum = 0.0f;

    // split-phase mapping: this thread owns column csp, k-half ksp
    const int csp = tid & 63;
    const int ksp = tid >> 6;            // 0/1 -> k in [24*ksp, 24*ksp+24)

    for (int base = 0; base < keff; base += KCH) {
        int jn = keff - base; if (jn > KCH) jn = KCH;

        __syncthreads();                 // Ht/Lt/yst free (prior mma done)

        // ---- build yst rows (zero-padded to KCH), coalesced 256B rows ----
        #pragma unroll
        for (int pass = 0; pass < 6; pass++) {
            int j  = (pass << 3) + (tid >> 4);
            int c4 = (tid & 15) << 2;
            float4 v = make_float4(0.f, 0.f, 0.f, 0.f);
            if (j < jn) {
                int i = ilo + base + j;
                int t = (i - smod) & 255;
                float aw = g_A[i];
                v = *(const float4*)(xb + (t << 6) + c4);
                v.x *= aw; v.y *= aw; v.z *= aw; v.w *= aw;
            }
            *(float4*)(&yst[j][c4]) = v;
        }
        __syncthreads();

        // ---- transpose + bf16 split + fused column sums ----
        {
            uint32_t ysrc = ybase + ((ksp * 24) << 8) + (csp << 2);
            uint32_t hdst = htb + csp * HSTB + ksp * 48;
            #pragma unroll
            for (int p = 0; p < 12; p++) {
                float y0 = __uint_as_float(lds32(ysrc));
                float y1 = __uint_as_float(lds32(ysrc + 256));
                msum += y0 + y1;
                uint32_t hp;
                asm("cvt.rn.bf16x2.f32 %0, %1, %2;" : "=r"(hp) : "f"(y1), "f"(y0));
                float h0 = __uint_as_float(hp << 16);
                float h1 = __uint_as_float(hp & 0xFFFF0000u);
                float l0 = y0 - h0;
                float l1 = y1 - h1;
                uint32_t lp;
                asm("cvt.rn.bf16x2.f32 %0, %1, %2;" : "=r"(lp) : "f"(l1), "f"(l0));
                sts32(hdst, hp);
                sts32(hdst + (ltb - htb), lp);
                ysrc += 512;             // 2 k-rows
                hdst += 4;               // 2 bf16
            }
        }
        __syncthreads();

        // ---- mma mainloop ----
        int nks = (jn + 15) >> 4;
        uint32_t aH = htb + (m0 + g) * HSTB + (tig << 2);
        uint32_t aL = ltb + (m0 + g) * HSTB + (tig << 2);
        uint32_t bB = htb + g * HSTB + (tig << 2);
        const uint32_t LH = ltb - htb;

        #pragma unroll 1
        for (int ks = 0; ks < nks; ks++) {
            uint32_t ko = ks << 5;       // 16 k * 2B
            uint32_t ah[4], al[4];
            ah[0] = lds32(aH + ko);        ah[1] = lds32(aH + ko + 8 * HSTB);
            ah[2] = lds32(aH + ko + 16);   ah[3] = lds32(aH + ko + 8 * HSTB + 16);
            al[0] = lds32(aL + ko);        al[1] = lds32(aL + ko + 8 * HSTB);
            al[2] = lds32(aL + ko + 16);   al[3] = lds32(aL + ko + 8 * HSTB + 16);
            #pragma unroll
            for (int nt = 0; nt < 8; nt++) {
                uint32_t bb = bB + nt * (8 * HSTB) + ko;
                uint32_t bh[2], bl[2];
                bh[0] = lds32(bb);        bh[1] = lds32(bb + 16);
                bl[0] = lds32(bb + LH);   bl[1] = lds32(bb + LH + 16);
                mma_bf16(D[nt], ah, bh);  // H^T H
                mma_bf16(D[nt], ah, bl);  // H^T L
                mma_bf16(D[nt], al, bh);  // L^T H
            }
        }
    }

    // ---- column sums ----
    mpart[ksp][csp] = msum;
    __syncthreads();
    if (tid < 64) mcol[tid] = mpart[0][tid] + mpart[1][tid];
    __syncthreads();

    // ---- diagonal -> dinv ----
    const float inv256 = 1.0f / 256.0f;
    const int c1 = m0 + g;
    const int c2 = m0 + g + 8;
    if (tig == (g >> 1)) {
        int e = g & 1;
        float m1 = mcol[c1];
        float m2 = mcol[c2];
        dinv[c1] = rsqrtf(D[2 * wid][e]         - m1 * m1 * inv256);
        dinv[c2] = rsqrtf(D[2 * wid + 1][2 + e] - m2 * m2 * inv256);
    }
    __syncthreads();

    // ---- normalize, clip, write (float2 = 32B L2 sectors per row-segment) ----
    float mc1 = mcol[c1] * inv256, mc2 = mcol[c2] * inv256;
    float dc1 = dinv[c1],          dc2 = dinv[c2];
    float* ob = out + (((size_t)(b * NWIN + w)) << 12);
    #pragma unroll
    for (int nt = 0; nt < 8; nt++) {
        int d0 = (nt << 3) + (tig << 1);
        float md0 = mcol[d0], md1 = mcol[d0 + 1];
        float dd0 = dinv[d0], dd1 = dinv[d0 + 1];
        float2 v1, v2;
        v1.x = (D[nt][0] - mc1 * md0) * dc1 * dd0;
        v1.y = (D[nt][1] - mc1 * md1) * dc1 * dd1;
        v2.x = (D[nt][2] - mc2 * md0) * dc2 * dd0;
        v2.y = (D[nt][3] - mc2 * md1) * dc2 * dd1;
        v1.x = fminf(1.0f, fmaxf(-1.0f, v1.x));
        v1.y = fminf(1.0f, fmaxf(-1.0f, v1.y));
        v2.x = fminf(1.0f, fmaxf(-1.0f, v2.x));
        v2.y = fminf(1.0f, fmaxf(-1.0f, v2.y));
        *(float2*)(ob + (c1 << 6) + d0) = v1;
        *(float2*)(ob + (c2 << 6) + d0) = v2;
    }
}

// ---------------------------------------------------------------------------
extern "C" void kernel_launch(void* const* d_in, const int* in_sizes, int n_in,
                              void* d_out, int out_size) {
    const float* x     = (const float*)d_in[0];   // (16, 256, 64) fp32
    const float* alpha = (const float*)d_in[1];   // (1,) fp32
    float* out = (float*)d_out;                   // (16, 224, 64, 64) fp32

    prep_kernel<<<1, 512>>>(alpha);
    dim3 grid(NWIN, B_DIM);
    corr_kernel<<<grid, 128>>>(x, out);
}

// round 11
// speedup vs baseline: 1.0556x; 1.0556x over previous
#include <cuda_runtime.h>
#include <cstdint>

// SlidingGaussianWindow1d: out[b,w,c,d] = clip(corrcoef_t of x[b,t,:] * W[w,t])
// B=16, T=256, C=64, NWIN=224.
//
// Identities:
//  - W[w,t] = A[(t + S_w) mod 256], S_w = (w+1)(w-222)/2
//  - A = conv(gauss, box)/max ~0 outside a ~40-wide arc: truncate t-loop to
//    the support (found on device; chunked fallback for wide alpha).
//  - corr_cd = (S_cd - m_c m_d/T) * dinv_c * dinv_d (1/(T-1) cancels)
//
// R11: R10 with ldmatrix-legal operand stride. 112B row stride (7x16):
// 16B-aligned rows (ldmatrix requirement) AND conflict-free (112r mod 128
// tiles all banks across 8 rows). mma.sync.m16n8k16.bf16, split y = hi+lo,
// S ~= HtH + HtL + LtH; operands built straight from gmem.

#define T_LEN 256
#define C_DIM 64
#define NWIN  224
#define B_DIM 16
#define KCH   48            // K-chunk (padded); support arc fits in one chunk
#define HSTB  112           // Ht/Lt row stride in bytes (16B-aligned, 7x16)

__device__ float g_A[256];
__device__ int   g_ilo;
__device__ int   g_keff;

// ---------------------------------------------------------------------------
// Prep: A[t] from win_alpha; parallel support scan {i : A[i] > 1e-6}.
// ---------------------------------------------------------------------------
__global__ void prep_kernel(const float* __restrict__ alpha) {
    __shared__ float gw[256];
    __shared__ float Ac[511];
    __shared__ float red[64];
    __shared__ float sA[256];
    __shared__ float s_max;
    __shared__ unsigned int masks[8];
    int tid = threadIdx.x;  // 512 threads

    float a = alpha[0];
    float inv = 1.0f / (2.0f * a * a);
    if (tid < 256) {
        float d = (float)tid - 128.0f;
        gw[tid] = expf(-d * d) * inv;
    }
    __syncthreads();
    if (tid < 511) {
        int lo = tid - 143; if (lo < 0)   lo = 0;
        int hi = tid - 112; if (hi > 255) hi = 255;
        float s = 0.0f;
        for (int k = lo; k <= hi; k++) s += gw[k];
        Ac[tid] = s;
    }
    __syncthreads();
    if (tid < 64) {
        float m = 0.0f;
        for (int n = tid; n < 511; n += 64) m = fmaxf(m, Ac[n]);
        red[tid] = m;
    }
    __syncthreads();
    if (tid == 0) {
        float m = 0.0f;
        #pragma unroll
        for (int n = 0; n < 64; n++) m = fmaxf(m, red[n]);
        s_max = m;
    }
    __syncthreads();
    if (tid < 256) {
        float v = Ac[128 + tid] / s_max;
        sA[tid] = v;
        g_A[tid] = v;
    }
    __syncthreads();
    if (tid < 256) {
        unsigned int m = __ballot_sync(0xFFFFFFFFu, sA[tid] > 1e-6f);
        if ((tid & 31) == 0) masks[tid >> 5] = m;
    }
    __syncthreads();
    if (tid == 0) {
        int lo = 0, hi = 255;
        for (int k = 0; k < 8; k++)
            if (masks[k]) { lo = k * 32 + __ffs(masks[k]) - 1; break; }
        for (int k = 7; k >= 0; k--)
            if (masks[k]) { hi = k * 32 + 31 - __clz(masks[k]); break; }
        g_ilo  = lo;
        g_keff = hi - lo + 1;
    }
}

// ---------------------------------------------------------------------------
__device__ __forceinline__ void mma_bf16(float* d, const uint32_t* a, const uint32_t* b) {
    asm volatile(
        "mma.sync.aligned.m16n8k16.row.col.f32.bf16.bf16.f32 "
        "{%0,%1,%2,%3}, {%4,%5,%6,%7}, {%8,%9}, {%0,%1,%2,%3};"
        : "+f"(d[0]), "+f"(d[1]), "+f"(d[2]), "+f"(d[3])
        : "r"(a[0]), "r"(a[1]), "r"(a[2]), "r"(a[3]), "r"(b[0]), "r"(b[1]));
}
__device__ __forceinline__ void ldmx4(uint32_t* r, uint32_t addr) {
    asm volatile("ldmatrix.sync.aligned.m8n8.x4.shared.b16 {%0,%1,%2,%3}, [%4];"
                 : "=r"(r[0]), "=r"(r[1]), "=r"(r[2]), "=r"(r[3]) : "r"(addr));
}
__device__ __forceinline__ void sts32(uint32_t addr, uint32_t v) {
    asm volatile("st.shared.b32 [%0], %1;" :: "r"(addr), "r"(v));
}

// ---------------------------------------------------------------------------
// Main: 128 threads per (w, b). Warp wid owns c-strip [16wid, 16wid+16)
// (one m16 tile row) x all 64 d (8 n-tiles). 3 mma chains: HH, HL, LH.
// Operands Ht/Lt: bf16 [c][k] rows, stride 112B, built straight from gmem.
// ---------------------------------------------------------------------------
__global__ __launch_bounds__(128, 8) void corr_kernel(const float* __restrict__ x,
                                                      float* __restrict__ out) {
    __shared__ __align__(16) uint32_t Hts[(64 * HSTB) / 4];  // 7 KB
    __shared__ __align__(16) uint32_t Lts[(64 * HSTB) / 4];
    __shared__ float mpart[2][64];
    __shared__ float mcol[64];
    __shared__ float dinv[64];

    const int w    = blockIdx.x;
    const int b    = blockIdx.y;
    const int tid  = threadIdx.x;
    const int wid  = tid >> 5;
    const int lane = tid & 31;
    const int g    = lane >> 2;          // fragment group row
    const int tig  = lane & 3;           // thread-in-group

    int s = ((w + 1) * (w - 222)) / 2;   // cumulative roll (even product, exact)
    int smod = ((s % 256) + 256) & 255;

    const int ilo  = g_ilo;
    const int keff = g_keff;

    const float* xb = x + ((size_t)b << 14);
    const int m0 = wid << 4;

    const uint32_t htb = (uint32_t)__cvta_generic_to_shared(&Hts[0]);
    const uint32_t ltb = (uint32_t)__cvta_generic_to_shared(&Lts[0]);
    const uint32_t LH  = ltb - htb;

    // ldmatrix per-lane address offsets (bytes) into the [c][k] buffers.
    // A (m16k16): matrices {m0k0, m8k0, m0k8, m8k8} -> m_add=(mat&1)*8, k_add=(mat>>1)*8
    const int matA = lane >> 3;
    const uint32_t offA = (uint32_t)((m0 + (lane & 7) + (matA & 1) * 8) * HSTB + (matA >> 1) * 16);
    // B (two n8k16 tiles/ldmatrix): matrices {n0k0, n0k8, n8k0, n8k8}
    const uint32_t offB = (uint32_t)(((lane & 7) + (lane >> 4) * 8) * HSTB + ((lane >> 3) & 1) * 16);

    float D[8][4];
    #pragma unroll
    for (int nt = 0; nt < 8; nt++)
        #pragma unroll
        for (int e = 0; e < 4; e++) D[nt][e] = 0.0f;
    float msum = 0.0f;

    // build mapping: thread owns column csp, k-half ksp (24 k each)
    const int csp = tid & 63;
    const int ksp = tid >> 6;

    for (int base = 0; base < keff; base += KCH) {
        int jn = keff - base; if (jn > KCH) jn = KCH;
        if (base) __syncthreads();       // guard operand reuse across chunks

        // ---- build Ht/Lt straight from gmem (coalesced 128B per k per warp) ----
        {
            uint32_t hdst = htb + csp * HSTB + ksp * 48;
            #pragma unroll
            for (int q = 0; q < 12; q++) {
                int j0 = 24 * ksp + 2 * q;
                int i0 = ilo + base + j0;
                float y0 = 0.0f, y1 = 0.0f;
                if (j0 < jn) {
                    int t = (i0 - smod) & 255;
                    y0 = xb[(t << 6) + csp] * g_A[i0];
                }
                if (j0 + 1 < jn) {
                    int t = (i0 + 1 - smod) & 255;
                    y1 = xb[(t << 6) + csp] * g_A[i0 + 1];
                }
                msum += y0 + y1;
                uint32_t hp;
                asm("cvt.rn.bf16x2.f32 %0, %1, %2;" : "=r"(hp) : "f"(y1), "f"(y0));
                float h0 = __uint_as_float(hp << 16);
                float h1 = __uint_as_float(hp & 0xFFFF0000u);
                float l0 = y0 - h0;
                float l1 = y1 - h1;
                uint32_t lp;
                asm("cvt.rn.bf16x2.f32 %0, %1, %2;" : "=r"(lp) : "f"(l1), "f"(l0));
                sts32(hdst + 4 * q, hp);
                sts32(hdst + LH + 4 * q, lp);
            }
        }
        __syncthreads();

        // ---- mma mainloop: ldmatrix fragments, 3 chains ----
        int nks = (jn + 15) >> 4;
        #pragma unroll 3
        for (int ks = 0; ks < nks; ks++) {
            uint32_t ko = (uint32_t)(ks << 5);   // 16 k * 2B
            uint32_t aH[4], aL[4];
            ldmx4(aH, htb + offA + ko);
            ldmx4(aL, ltb + offA + ko);
            #pragma unroll
            for (int p = 0; p < 4; p++) {
                uint32_t bh[4], bl[4];
                uint32_t bo = offB + (uint32_t)(p * 16 * HSTB) + ko;
                ldmx4(bh, htb + bo);
                ldmx4(bl, ltb + bo);
                mma_bf16(D[2 * p],     aH, bh);      // H^T H   (n-tile 2p)
                mma_bf16(D[2 * p],     aH, bl);      // H^T L
                mma_bf16(D[2 * p],     aL, bh);      // L^T H
                mma_bf16(D[2 * p + 1], aH, bh + 2);  // n-tile 2p+1
                mma_bf16(D[2 * p + 1], aH, bl + 2);
                mma_bf16(D[2 * p + 1], aL, bh + 2);
            }
        }
    }

    // ---- column sums ----
    mpart[ksp][csp] = msum;
    __syncthreads();
    if (tid < 64) mcol[tid] = mpart[0][tid] + mpart[1][tid];
    __syncthreads();

    // ---- diagonal -> dinv ----
    const float inv256 = 1.0f / 256.0f;
    const int c1 = m0 + g;
    const int c2 = m0 + g + 8;
    if (tig == (g >> 1)) {
        int e = g & 1;
        float m1 = mcol[c1];
        float m2 = mcol[c2];
        dinv[c1] = rsqrtf(D[2 * wid][e]         - m1 * m1 * inv256);
        dinv[c2] = rsqrtf(D[2 * wid + 1][2 + e] - m2 * m2 * inv256);
    }
    __syncthreads();

    // ---- normalize, clip, write (float2 = 32B L2 sectors per row-segment) ----
    float mc1 = mcol[c1] * inv256, mc2 = mcol[c2] * inv256;
    float dc1 = dinv[c1],          dc2 = dinv[c2];
    float* ob = out + (((size_t)(b * NWIN + w)) << 12);
    #pragma unroll
    for (int nt = 0; nt < 8; nt++) {
        int d0 = (nt << 3) + (tig << 1);
        float md0 = mcol[d0], md1 = mcol[d0 + 1];
        float dd0 = dinv[d0], dd1 = dinv[d0 + 1];
        float2 v1, v2;
        v1.x = (D[nt][0] - mc1 * md0) * dc1 * dd0;
        v1.y = (D[nt][1] - mc1 * md1) * dc1 * dd1;
        v2.x = (D[nt][2] - mc2 * md0) * dc2 * dd0;
        v2.y = (D[nt][3] - mc2 * md1) * dc2 * dd1;
        v1.x = fminf(1.0f, fmaxf(-1.0f, v1.x));
        v1.y = fminf(1.0f, fmaxf(-1.0f, v1.y));
        v2.x = fminf(1.0f, fmaxf(-1.0f, v2.x));
        v2.y = fminf(1.0f, fmaxf(-1.0f, v2.y));
        *(float2*)(ob + (c1 << 6) + d0) = v1;
        *(float2*)(ob + (c2 << 6) + d0) = v2;
    }
}

// ---------------------------------------------------------------------------
extern "C" void kernel_launch(void* const* d_in, const int* in_sizes, int n_in,
                              void* d_out, int out_size) {
    const float* x     = (const float*)d_in[0];   // (16, 256, 64) fp32
    const float* alpha = (const float*)d_in[1];   // (1,) fp32
    float* out = (float*)d_out;                   // (16, 224, 64, 64) fp32

    prep_kernel<<<1, 512>>>(alpha);
    dim3 grid(NWIN, B_DIM);
    corr_kernel<<<grid, 128>>>(x, out);
}

// round 12
// speedup vs baseline: 1.1177x; 1.0589x over previous
#include <cuda_runtime.h>
#include <cstdint>

// SlidingGaussianWindow1d: out[b,w,c,d] = clip(corrcoef_t of x[b,t,:] * W[w,t])
// B=16, T=256, C=64, NWIN=224.
//
// Identities:
//  - W[w,t] = A[(t + S_w) mod 256], S_w = (w+1)(w-222)/2
//  - A = conv(gauss, box)/max ~0 outside a ~40-wide arc: truncate t-loop to
//    the support (found on device; chunked fallback for wide alpha).
//  - corr_cd = (S_cd - m_c m_d/T) * dinv_c * dinv_d (1/(T-1) cancels)
//
// R12: mma.sync.m16n8k16.bf16, split y = hi+lo, S ~= HtH + HtL + LtH.
// vs R11: STS.128-packed operand build (4-wf floor, no conflict excess) and
// 2x2 warp tiling (warp = m32 x n32 block) to halve B-fragment redundancy.

#define T_LEN 256
#define C_DIM 64
#define NWIN  224
#define B_DIM 16
#define KCH   48            // K-chunk (padded); support arc fits in one chunk
#define HSTB  112           // Ht/Lt row stride in bytes (16B-aligned, 7x16)

__device__ float g_A[256];
__device__ int   g_ilo;
__device__ int   g_keff;

// ---------------------------------------------------------------------------
// Prep: A[t] from win_alpha; parallel support scan {i : A[i] > 1e-6}.
// ---------------------------------------------------------------------------
__global__ void prep_kernel(const float* __restrict__ alpha) {
    __shared__ float gw[256];
    __shared__ float Ac[511];
    __shared__ float red[64];
    __shared__ float sA[256];
    __shared__ float s_max;
    __shared__ unsigned int masks[8];
    int tid = threadIdx.x;  // 512 threads

    float a = alpha[0];
    float inv = 1.0f / (2.0f * a * a);
    if (tid < 256) {
        float d = (float)tid - 128.0f;
        gw[tid] = expf(-d * d) * inv;
    }
    __syncthreads();
    if (tid < 511) {
        int lo = tid - 143; if (lo < 0)   lo = 0;
        int hi = tid - 112; if (hi > 255) hi = 255;
        float s = 0.0f;
        for (int k = lo; k <= hi; k++) s += gw[k];
        Ac[tid] = s;
    }
    __syncthreads();
    if (tid < 64) {
        float m = 0.0f;
        for (int n = tid; n < 511; n += 64) m = fmaxf(m, Ac[n]);
        red[tid] = m;
    }
    __syncthreads();
    if (tid == 0) {
        float m = 0.0f;
        #pragma unroll
        for (int n = 0; n < 64; n++) m = fmaxf(m, red[n]);
        s_max = m;
    }
    __syncthreads();
    if (tid < 256) {
        float v = Ac[128 + tid] / s_max;
        sA[tid] = v;
        g_A[tid] = v;
    }
    __syncthreads();
    if (tid < 256) {
        unsigned int m = __ballot_sync(0xFFFFFFFFu, sA[tid] > 1e-6f);
        if ((tid & 31) == 0) masks[tid >> 5] = m;
    }
    __syncthreads();
    if (tid == 0) {
        int lo = 0, hi = 255;
        for (int k = 0; k < 8; k++)
            if (masks[k]) { lo = k * 32 + __ffs(masks[k]) - 1; break; }
        for (int k = 7; k >= 0; k--)
            if (masks[k]) { hi = k * 32 + 31 - __clz(masks[k]); break; }
        g_ilo  = lo;
        g_keff = hi - lo + 1;
    }
}

// ---------------------------------------------------------------------------
__device__ __forceinline__ void mma_bf16(float* d, const uint32_t* a, const uint32_t* b) {
    asm volatile(
        "mma.sync.aligned.m16n8k16.row.col.f32.bf16.bf16.f32 "
        "{%0,%1,%2,%3}, {%4,%5,%6,%7}, {%8,%9}, {%0,%1,%2,%3};"
        : "+f"(d[0]), "+f"(d[1]), "+f"(d[2]), "+f"(d[3])
        : "r"(a[0]), "r"(a[1]), "r"(a[2]), "r"(a[3]), "r"(b[0]), "r"(b[1]));
}
__device__ __forceinline__ void ldmx4(uint32_t* r, uint32_t addr) {
    asm volatile("ldmatrix.sync.aligned.m8n8.x4.shared.b16 {%0,%1,%2,%3}, [%4];"
                 : "=r"(r[0]), "=r"(r[1]), "=r"(r[2]), "=r"(r[3]) : "r"(addr));
}
__device__ __forceinline__ void sts128(uint32_t addr, uint32_t v0, uint32_t v1,
                                       uint32_t v2, uint32_t v3) {
    asm volatile("st.shared.v4.b32 [%0], {%1,%2,%3,%4};"
                 :: "r"(addr), "r"(v0), "r"(v1), "r"(v2), "r"(v3));
}

// ---------------------------------------------------------------------------
// Main: 128 threads per (w, b). 2x2 warp grid: warp wid owns the
// (m32 = (wid&1)*32, n32 = (wid>>1)*32) block of S. 3 mma chains: HH, HL, LH.
// Operands Ht/Lt: bf16 [c][k] rows, stride 112B, built straight from gmem
// with STS.128-packed stores.
// ---------------------------------------------------------------------------
__global__ __launch_bounds__(128, 8) void corr_kernel(const float* __restrict__ x,
                                                      float* __restrict__ out) {
    __shared__ __align__(16) uint32_t Hts[(64 * HSTB) / 4];  // 7 KB
    __shared__ __align__(16) uint32_t Lts[(64 * HSTB) / 4];
    __shared__ float mpart[2][64];
    __shared__ float mcol[64];
    __shared__ float dinv[64];

    const int w    = blockIdx.x;
    const int b    = blockIdx.y;
    const int tid  = threadIdx.x;
    const int wid  = tid >> 5;
    const int lane = tid & 31;
    const int g    = lane >> 2;          // fragment group row (0..7)
    const int tig  = lane & 3;           // thread-in-group

    int s = ((w + 1) * (w - 222)) / 2;   // cumulative roll (even product, exact)
    int smod = ((s % 256) + 256) & 255;

    const int ilo  = g_ilo;
    const int keff = g_keff;

    const float* xb = x + ((size_t)b << 14);
    const int mb = (wid & 1) << 5;       // warp m-base (rows of S)
    const int nb = (wid >> 1) << 5;      // warp n-base (cols of S)

    const uint32_t htb = (uint32_t)__cvta_generic_to_shared(&Hts[0]);
    const uint32_t ltb = (uint32_t)__cvta_generic_to_shared(&Lts[0]);
    const uint32_t LH  = ltb - htb;

    // ldmatrix per-lane offsets (bytes) into the [c][k] buffers.
    // A m16k16 (row-major): matrices {m0k0, m8k0, m0k8, m8k8}
    const int matA = lane >> 3;
    const uint32_t offA0 = (uint32_t)((mb + (lane & 7) + (matA & 1) * 8) * HSTB
                                      + (matA >> 1) * 16);
    // B pair of n8k16 (col-major): matrices {n0k0, n0k8, n8k0, n8k8}
    const uint32_t offB0 = (uint32_t)((nb + (lane & 7) + (lane >> 4) * 8) * HSTB
                                      + ((lane >> 3) & 1) * 16);

    float D[2][4][4];
    #pragma unroll
    for (int mt = 0; mt < 2; mt++)
        #pragma unroll
        for (int nt = 0; nt < 4; nt++)
            #pragma unroll
            for (int e = 0; e < 4; e++) D[mt][nt][e] = 0.0f;
    float msum = 0.0f;

    // build mapping: thread owns row csp, k-half ksp (24 k each)
    const int csp = tid & 63;
    const int ksp = tid >> 6;

    for (int base = 0; base < keff; base += KCH) {
        int jn = keff - base; if (jn > KCH) jn = KCH;
        if (base) __syncthreads();       // guard operand reuse across chunks

        // ---- build Ht/Lt from gmem; packed 16B stores ----
        {
            uint32_t hdst = htb + csp * HSTB + ksp * 48;
            #pragma unroll
            for (int g3 = 0; g3 < 3; g3++) {
                int k0 = ksp * 24 + g3 * 8;
                float y[8];
                #pragma unroll
                for (int u = 0; u < 8; u++) {
                    int j = k0 + u;
                    float v = 0.0f;
                    if (j < jn) {
                        int i = ilo + base + j;
                        int t = (i - smod) & 255;
                        v = xb[(t << 6) + csp] * g_A[i];
                    }
                    y[u] = v;
                    msum += v;
                }
                uint32_t hp[4], lp[4];
                #pragma unroll
                for (int v2 = 0; v2 < 4; v2++) {
                    float y0 = y[2 * v2], y1 = y[2 * v2 + 1];
                    uint32_t hpv;
                    asm("cvt.rn.bf16x2.f32 %0, %1, %2;" : "=r"(hpv) : "f"(y1), "f"(y0));
                    float h0 = __uint_as_float(hpv << 16);
                    float h1 = __uint_as_float(hpv & 0xFFFF0000u);
                    float l0 = y0 - h0;
                    float l1 = y1 - h1;
                    uint32_t lpv;
                    asm("cvt.rn.bf16x2.f32 %0, %1, %2;" : "=r"(lpv) : "f"(l1), "f"(l0));
                    hp[v2] = hpv;
                    lp[v2] = lpv;
                }
                sts128(hdst + g3 * 16,      hp[0], hp[1], hp[2], hp[3]);
                sts128(hdst + LH + g3 * 16, lp[0], lp[1], lp[2], lp[3]);
            }
        }
        __syncthreads();

        // ---- mma mainloop ----
        int nks = (jn + 15) >> 4;
        #pragma unroll 3
        for (int ks = 0; ks < nks; ks++) {
            uint32_t ko = (uint32_t)(ks << 5);   // 16 k * 2B
            uint32_t aH[2][4], aL[2][4];
            ldmx4(aH[0], htb + offA0 + ko);
            ldmx4(aH[1], htb + offA0 + (uint32_t)(16 * HSTB) + ko);
            ldmx4(aL[0], ltb + offA0 + ko);
            ldmx4(aL[1], ltb + offA0 + (uint32_t)(16 * HSTB) + ko);
            #pragma unroll
            for (int bt = 0; bt < 2; bt++) {
                uint32_t bo = offB0 + (uint32_t)(bt * 16 * HSTB) + ko;
                uint32_t bh[4], bl[4];
                ldmx4(bh, htb + bo);
                ldmx4(bl, ltb + bo);
                #pragma unroll
                for (int mt = 0; mt < 2; mt++) {
                    #pragma unroll
                    for (int pr = 0; pr < 2; pr++) {
                        float* Dp = D[mt][bt * 2 + pr];
                        mma_bf16(Dp, aH[mt], bh + 2 * pr);   // H^T H
                        mma_bf16(Dp, aH[mt], bl + 2 * pr);   // H^T L
                        mma_bf16(Dp, aL[mt], bh + 2 * pr);   // L^T H
                    }
                }
            }
        }
    }

    // ---- column sums ----
    mpart[ksp][csp] = msum;
    __syncthreads();
    if (tid < 64) mcol[tid] = mpart[0][tid] + mpart[1][tid];
    __syncthreads();

    // ---- diagonal -> dinv (diag warps: mb == nb, i.e. wid 0 and 3) ----
    const float inv256 = 1.0f / 256.0f;
    if (mb == nb && tig == (g >> 1)) {
        #pragma unroll
        for (int mt = 0; mt < 2; mt++) {
            #pragma unroll
            for (int rh = 0; rh < 2; rh++) {
                int c = mb + mt * 16 + rh * 8 + g;
                int nt = mt * 2 + rh;
                int e  = (g & 1) + rh * 2;
                float m = mcol[c];
                dinv[c] = rsqrtf(D[mt][nt][e] - m * m * inv256);
            }
        }
    }
    __syncthreads();

    // ---- normalize, clip, write (float2 = 32B L2 sectors per row-segment) ----
    float* ob = out + (((size_t)(b * NWIN + w)) << 12);
    const int d0 = nb + (tig << 1);
    #pragma unroll
    for (int mt = 0; mt < 2; mt++) {
        #pragma unroll
        for (int rh = 0; rh < 2; rh++) {
            int c = mb + mt * 16 + rh * 8 + g;
            float mc = mcol[c] * inv256;
            float dc = dinv[c];
            #pragma unroll
            for (int nt = 0; nt < 4; nt++) {
                int d = d0 + nt * 8;
                float md0 = mcol[d], md1 = mcol[d + 1];
                float dd0 = dinv[d], dd1 = dinv[d + 1];
                float2 v;
                v.x = (D[mt][nt][rh * 2 + 0] - mc * md0) * dc * dd0;
                v.y = (D[mt][nt][rh * 2 + 1] - mc * md1) * dc * dd1;
                v.x = fminf(1.0f, fmaxf(-1.0f, v.x));
                v.y = fminf(1.0f, fmaxf(-1.0f, v.y));
                *(float2*)(ob + (c << 6) + d) = v;
            }
        }
    }
}

// ---------------------------------------------------------------------------
extern "C" void kernel_launch(void* const* d_in, const int* in_sizes, int n_in,
                              void* d_out, int out_size) {
    const float* x     = (const float*)d_in[0];   // (16, 256, 64) fp32
    const float* alpha = (const float*)d_in[1];   // (1,) fp32
    float* out = (float*)d_out;                   // (16, 224, 64, 64) fp32

    prep_kernel<<<1, 512>>>(alpha);
    dim3 grid(NWIN, B_DIM);
    corr_kernel<<<grid, 128>>>(x, out);
}